// round 14
// baseline (speedup 1.0000x reference)
#include <cuda_runtime.h>

// GEMV: y = alpha * (A @ x) + beta * b   — FINAL
//
// A: [16384,16384] f32 read exactly once = 1.074 GB compulsory HBM traffic.
// Sustained HBM rate measured across 13 structural variants: 7.0-7.06 TB/s
// (88-89% of spec; the practical DRAM ceiling on GB300 for this pattern).
// Floor = 1.074 GB / 7.05 TB/s ~= 150 us; this kernel measures 150.0 us.
//
// Structure (each element validated by A/B measurement):
//  - one CTA per row: contiguous 64KB sequential DRAM stream per CTA
//  - __ldcs A (evict-first), __ldg x (L1-resident; L1 persists within launch)
//  - unroll 4: front-batched independent LDG.128s (ample MLP)
//  - __launch_bounds__(256,8): 32 regs -> 2048 threads/SM (occupancy was the
//    decisive lever: DRAM% tracked occ across 56/70/94% occ points)
// Exhausted alternatives (neutral or worse): RPB=2/4, LDG.256, persistent
// grid, split streams, TPB=512, higher unroll. TMA excluded: chip throughput
// cap is path-independent (LDG.cv == TMA per B300 microarch measurements).

#define ROWS 16384
#define COLS 16384
#define TPB  256

__global__ __launch_bounds__(TPB, 8) void gemv_kernel(
    const float* __restrict__ alpha,
    const float* __restrict__ A,
    const float* __restrict__ x,
    const float* __restrict__ beta,
    const float* __restrict__ b,
    float* __restrict__ y)
{
    const int row = blockIdx.x;
    const int tid = threadIdx.x;

    const float4* __restrict__ arow = reinterpret_cast<const float4*>(A + (size_t)row * COLS);
    const float4* __restrict__ xv   = reinterpret_cast<const float4*>(x);

    float acc = 0.0f;

    // COLS/4 = 4096 float4; 256 threads -> 16 iterations; unroll 4.
    #pragma unroll 4
    for (int i = tid; i < COLS / 4; i += TPB) {
        float4 a = __ldcs(&arow[i]);
        float4 v = __ldg(&xv[i]);
        acc = fmaf(a.x, v.x, acc);
        acc = fmaf(a.y, v.y, acc);
        acc = fmaf(a.z, v.z, acc);
        acc = fmaf(a.w, v.w, acc);
    }

    // warp reduce
    #pragma unroll
    for (int off = 16; off > 0; off >>= 1)
        acc += __shfl_xor_sync(0xFFFFFFFFu, acc, off);

    __shared__ float warp_sums[TPB / 32];
    const int lane = tid & 31;
    const int wid  = tid >> 5;
    if (lane == 0) warp_sums[wid] = acc;
    __syncthreads();

    if (wid == 0) {
        float s = (lane < TPB / 32) ? warp_sums[lane] : 0.0f;
        #pragma unroll
        for (int off = 4; off > 0; off >>= 1)
            s += __shfl_xor_sync(0xFFFFFFFFu, s, off);
        if (lane == 0)
            y[row] = alpha[0] * s + beta[0] * b[row];
    }
}

extern "C" void kernel_launch(void* const* d_in, const int* in_sizes, int n_in,
                              void* d_out, int out_size) {
    const float* alpha = (const float*)d_in[0];
    const float* A     = (const float*)d_in[1];
    const float* x     = (const float*)d_in[2];
    const float* beta  = (const float*)d_in[3];
    const float* b     = (const float*)d_in[4];
    float* y = (float*)d_out;

    gemv_kernel<<<ROWS, TPB>>>(alpha, A, x, beta, b, y);
}

// round 15
// speedup vs baseline: 1.0015x; 1.0015x over previous
#include <cuda_runtime.h>

// GEMV: y = alpha * (A @ x) + beta * b
// Final structure (one row/CTA, ldcs A, ldg x, launch_bounds(256,8)) with
// unroll 8: doubles the front-batched independent LDG.128 window vs unroll 4
// (the unroll 2->4 step measured ~2us). 16 trips total -> 2 unrolled passes.

#define ROWS 16384
#define COLS 16384
#define TPB  256

__global__ __launch_bounds__(TPB, 8) void gemv_kernel(
    const float* __restrict__ alpha,
    const float* __restrict__ A,
    const float* __restrict__ x,
    const float* __restrict__ beta,
    const float* __restrict__ b,
    float* __restrict__ y)
{
    const int row = blockIdx.x;
    const int tid = threadIdx.x;

    const float4* __restrict__ arow = reinterpret_cast<const float4*>(A + (size_t)row * COLS);
    const float4* __restrict__ xv   = reinterpret_cast<const float4*>(x);

    float acc = 0.0f;

    // COLS/4 = 4096 float4; 256 threads -> 16 iterations; unroll 8.
    #pragma unroll 8
    for (int i = tid; i < COLS / 4; i += TPB) {
        float4 a = __ldcs(&arow[i]);
        float4 v = __ldg(&xv[i]);
        acc = fmaf(a.x, v.x, acc);
        acc = fmaf(a.y, v.y, acc);
        acc = fmaf(a.z, v.z, acc);
        acc = fmaf(a.w, v.w, acc);
    }

    // warp reduce
    #pragma unroll
    for (int off = 16; off > 0; off >>= 1)
        acc += __shfl_xor_sync(0xFFFFFFFFu, acc, off);

    __shared__ float warp_sums[TPB / 32];
    const int lane = tid & 31;
    const int wid  = tid >> 5;
    if (lane == 0) warp_sums[wid] = acc;
    __syncthreads();

    if (wid == 0) {
        float s = (lane < TPB / 32) ? warp_sums[lane] : 0.0f;
        #pragma unroll
        for (int off = 4; off > 0; off >>= 1)
            s += __shfl_xor_sync(0xFFFFFFFFu, s, off);
        if (lane == 0)
            y[row] = alpha[0] * s + beta[0] * b[row];
    }
}

extern "C" void kernel_launch(void* const* d_in, const int* in_sizes, int n_in,
                              void* d_out, int out_size) {
    const float* alpha = (const float*)d_in[0];
    const float* A     = (const float*)d_in[1];
    const float* x     = (const float*)d_in[2];
    const float* beta  = (const float*)d_in[3];
    const float* b     = (const float*)d_in[4];
    float* y = (float*)d_out;

    gemv_kernel<<<ROWS, TPB>>>(alpha, A, x, beta, b, y);
}

// round 16
// speedup vs baseline: 1.0060x; 1.0045x over previous
#include <cuda_runtime.h>

// GEMV: y = alpha * (A @ x) + beta * b   — final-candidate
// One row/CTA, ldcs A, ldg x, launch_bounds(256,8)=32regs/94% occ.
// FULL unroll (16): entire per-thread trip is straight-line; ptxas
// front-batches the max LDG.128 window the 32-reg budget allows, zero loop
// overhead. Unroll trend measured monotone: 2:88.2% -> 4:89.5% -> 8:89.9% DRAM.

#define ROWS 16384
#define COLS 16384
#define TPB  256

__global__ __launch_bounds__(TPB, 8) void gemv_kernel(
    const float* __restrict__ alpha,
    const float* __restrict__ A,
    const float* __restrict__ x,
    const float* __restrict__ beta,
    const float* __restrict__ b,
    float* __restrict__ y)
{
    const int row = blockIdx.x;
    const int tid = threadIdx.x;

    const float4* __restrict__ arow = reinterpret_cast<const float4*>(A + (size_t)row * COLS);
    const float4* __restrict__ xv   = reinterpret_cast<const float4*>(x);

    float acc = 0.0f;

    // COLS/4 = 4096 float4; 256 threads -> exactly 16 iterations; fully unrolled.
    #pragma unroll 16
    for (int i = tid; i < COLS / 4; i += TPB) {
        float4 a = __ldcs(&arow[i]);
        float4 v = __ldg(&xv[i]);
        acc = fmaf(a.x, v.x, acc);
        acc = fmaf(a.y, v.y, acc);
        acc = fmaf(a.z, v.z, acc);
        acc = fmaf(a.w, v.w, acc);
    }

    // warp reduce
    #pragma unroll
    for (int off = 16; off > 0; off >>= 1)
        acc += __shfl_xor_sync(0xFFFFFFFFu, acc, off);

    __shared__ float warp_sums[TPB / 32];
    const int lane = tid & 31;
    const int wid  = tid >> 5;
    if (lane == 0) warp_sums[wid] = acc;
    __syncthreads();

    if (wid == 0) {
        float s = (lane < TPB / 32) ? warp_sums[lane] : 0.0f;
        #pragma unroll
        for (int off = 4; off > 0; off >>= 1)
            s += __shfl_xor_sync(0xFFFFFFFFu, s, off);
        if (lane == 0)
            y[row] = alpha[0] * s + beta[0] * b[row];
    }
}

extern "C" void kernel_launch(void* const* d_in, const int* in_sizes, int n_in,
                              void* d_out, int out_size) {
    const float* alpha = (const float*)d_in[0];
    const float* A     = (const float*)d_in[1];
    const float* x     = (const float*)d_in[2];
    const float* beta  = (const float*)d_in[3];
    const float* b     = (const float*)d_in[4];
    float* y = (float*)d_out;

    gemv_kernel<<<ROWS, TPB>>>(alpha, A, x, beta, b, y);
}

// round 17
// speedup vs baseline: 1.0202x; 1.0141x over previous
#include <cuda_runtime.h>

// GEMV: y = alpha * (A @ x) + beta * b   — FINAL (best of 16-round session)
//
// A: [16384,16384] f32 read exactly once = 1.074 GB compulsory HBM traffic.
// Sustained rate 7.0-7.13 TB/s (88-90% of spec) across every fully-occupied
// structure tested -> ~150 us floor; this kernel measures 149.3 us wall.
//
// Structure (each element A/B-validated over 16 rounds):
//  - one CTA per 64KB contiguous row (best DRAM sequentiality; RPB=2/4 worse)
//  - __ldcs A (evict-first streaming), __ldg x (L1-resident, 64 KB)
//  - FULL unroll (16): straight-line body, max front-batched LDG.128 window,
//    zero loop overhead (unroll sweep 2/4/8/16 monotone: 152.3->149.3 us)
//  - __launch_bounds__(256,8): 32 regs -> 2048 threads/SM (~94% occ; occupancy
//    was the decisive lever: DRAM% tracked occ at 56/70/94% points)
// Rejected by measurement: LDG.256 (within-LDG replays), persistent grid
// (imbalance + occ loss), TPB=512, multi-row CTAs. TMA excluded: chip
// throughput cap is path-independent (LDG.cv == TMA on B300).

#define ROWS 16384
#define COLS 16384
#define TPB  256

__global__ __launch_bounds__(TPB, 8) void gemv_kernel(
    const float* __restrict__ alpha,
    const float* __restrict__ A,
    const float* __restrict__ x,
    const float* __restrict__ beta,
    const float* __restrict__ b,
    float* __restrict__ y)
{
    const int row = blockIdx.x;
    const int tid = threadIdx.x;

    const float4* __restrict__ arow = reinterpret_cast<const float4*>(A + (size_t)row * COLS);
    const float4* __restrict__ xv   = reinterpret_cast<const float4*>(x);

    float acc = 0.0f;

    // COLS/4 = 4096 float4; 256 threads -> exactly 16 iterations; fully unrolled.
    #pragma unroll 16
    for (int i = tid; i < COLS / 4; i += TPB) {
        float4 a = __ldcs(&arow[i]);
        float4 v = __ldg(&xv[i]);
        acc = fmaf(a.x, v.x, acc);
        acc = fmaf(a.y, v.y, acc);
        acc = fmaf(a.z, v.z, acc);
        acc = fmaf(a.w, v.w, acc);
    }

    // warp reduce
    #pragma unroll
    for (int off = 16; off > 0; off >>= 1)
        acc += __shfl_xor_sync(0xFFFFFFFFu, acc, off);

    __shared__ float warp_sums[TPB / 32];
    const int lane = tid & 31;
    const int wid  = tid >> 5;
    if (lane == 0) warp_sums[wid] = acc;
    __syncthreads();

    if (wid == 0) {
        float s = (lane < TPB / 32) ? warp_sums[lane] : 0.0f;
        #pragma unroll
        for (int off = 4; off > 0; off >>= 1)
            s += __shfl_xor_sync(0xFFFFFFFFu, s, off);
        if (lane == 0)
            y[row] = alpha[0] * s + beta[0] * b[row];
    }
}

extern "C" void kernel_launch(void* const* d_in, const int* in_sizes, int n_in,
                              void* d_out, int out_size) {
    const float* alpha = (const float*)d_in[0];
    const float* A     = (const float*)d_in[1];
    const float* x     = (const float*)d_in[2];
    const float* beta  = (const float*)d_in[3];
    const float* b     = (const float*)d_in[4];
    float* y = (float*)d_out;

    gemv_kernel<<<ROWS, TPB>>>(alpha, A, x, beta, b, y);
}